// round 5
// baseline (speedup 1.0000x reference)
#include <cuda_runtime.h>

#define B_  32
#define G_  256
#define P_  2048
#define NC_ 80

#define CHUNKS_   8                    // blocks per batch
#define PRED_BLK_ (P_ / CHUNKS_)       // 256 preds per block (1 per thread)
#define NBLOCKS_  (CHUNKS_ * B_)       // 256

#define MW_ (G_ / 32)                  // mask words per class = 8

__device__ double   g_sum;     // zero at load; reset by last block each run
__device__ unsigned g_done;

// ---------------------------------------------------------------------------
// Single fused kernel. grid = (CHUNKS_, B_), block = 256, 1 pred/thread.
// Staging: per-class GT bitmask (atomicOr) + boxes in original g order +
// precomputed GT areas + pre_label histogram. No sort, no prefix, no scatter.
// Scoring: walk own class's mask from the TOP bit down => candidates in
// descending g; first giou>0 == reference's last valid index => early exit.
// ---------------------------------------------------------------------------
__global__ void __launch_bounds__(256)
fused_giou_kernel(const float* __restrict__ imgs_box,
                  const int*   __restrict__ img_labels,
                  const float* __restrict__ pre_BOX,
                  const int*   __restrict__ pre_label,
                  float*       __restrict__ out)
{
    const int b     = blockIdx.y;
    const int chunk = blockIdx.x;
    const int tid   = threadIdx.x;          // == GT index g during staging

    __shared__ float4   s_gbox[G_];         // GT boxes, original g order
    __shared__ float    s_ta[G_];           // precomputed GT areas
    __shared__ unsigned s_mask[NC_ * MW_];  // per-class membership bitmask (640 words)
    __shared__ int      s_phist[NC_];       // pre_label histogram (loss weights)
    __shared__ float    s_wsum[8];

    // --- zero masks + weight hist ---
    #pragma unroll
    for (int i = tid; i < NC_ * MW_; i += 256) s_mask[i] = 0u;
    if (tid < NC_) s_phist[tid] = 0;
    __syncthreads();

    // --- stage GT: box, area, class-mask bit ---
    {
        const int    lab = img_labels[b * G_ + tid];
        const float4 tb  = reinterpret_cast<const float4*>(imgs_box)[b * G_ + tid];
        s_gbox[tid] = tb;
        const float tw = fmaxf(tb.z - tb.x + 1.0f, 0.0f);
        const float th = fmaxf(tb.w - tb.y + 1.0f, 0.0f);
        s_ta[tid] = tw * th;
        atomicOr(&s_mask[lab * MW_ + (tid >> 5)], 1u << (tid & 31));
    }

    // --- prediction-label histogram (weights), int4-vectorized ---
    {
        const int4* pl4 = reinterpret_cast<const int4*>(pre_label + b * P_);
        #pragma unroll
        for (int i = 0; i < P_ / (4 * 256); ++i) {     // 2 iterations
            const int4 v = pl4[i * 256 + tid];
            atomicAdd(&s_phist[v.x], 1);
            atomicAdd(&s_phist[v.y], 1);
            atomicAdd(&s_phist[v.z], 1);
            atomicAdd(&s_phist[v.w], 1);
        }
    }
    __syncthreads();

    // --- score one prediction per thread ---
    const int p = chunk * PRED_BLK_ + tid;

    const float4 pb   = reinterpret_cast<const float4*>(pre_BOX)[b * P_ + p];
    const int    plab = pre_label[b * P_ + p];

    const float pw  = fmaxf(pb.z - pb.x + 1.0f, 0.0f);
    const float ph  = fmaxf(pb.w - pb.y + 1.0f, 0.0f);
    const float pa  = pw * ph;
    const float rpa = __fdividef(1.0f, pa);

    float loss = 0.0f;
    {
        const int mbase = plab * MW_;
        for (int w = MW_ - 1; w >= 0; --w) {
            unsigned m = s_mask[mbase + w];
            while (m) {
                const int bit = 31 - __clz(m);
                m &= ~(1u << bit);
                const int g = (w << 5) | bit;

                const float4 tb = s_gbox[g];
                const float  ta = s_ta[g];

                const float iw = fmaxf(fminf(pb.z, tb.z) - fmaxf(pb.x, tb.x) + 1.0f, 0.0f);
                const float ih = fmaxf(fminf(pb.w, tb.w) - fmaxf(pb.y, tb.y) + 1.0f, 0.0f);
                const float inter = iw * ih;
                const float uni   = pa + ta - inter;

                const float iou = fmaxf(inter * rpa, 1e-6f);   // reference: / pred area

                const float ow = fmaxf(fmaxf(pb.z, tb.z) - fminf(pb.x, tb.x) + 1.0f, 0.0f);
                const float oh = fmaxf(fmaxf(pb.w, tb.w) - fminf(pb.y, tb.y) + 1.0f, 0.0f);
                const float outer = ow * oh;

                float giou = iou - __fdividef(outer - uni, outer);
                giou = fminf(fmaxf(giou, -1.0f), 1.0f);

                if (giou > 0.0f) {           // first hit in descending g == last_idx
                    loss = 1.0f - giou;
                    goto scored;
                }
            }
        }
    }
scored:
    ;
    float acc = loss * (float)s_phist[plab];

    // --- block reduction ---
    #pragma unroll
    for (int off = 16; off > 0; off >>= 1)
        acc += __shfl_down_sync(0xFFFFFFFFu, acc, off);

    const int wid = tid >> 5, lid = tid & 31;
    if (lid == 0) s_wsum[wid] = acc;
    __syncthreads();
    if (wid == 0) {
        float v = (lid < 8) ? s_wsum[lid] : 0.0f;
        #pragma unroll
        for (int off = 4; off > 0; off >>= 1)
            v += __shfl_down_sync(0xFFFFFFFFu, v, off);
        if (lid == 0) {
            atomicAdd(&g_sum, (double)v);
            __threadfence();
            const unsigned t = atomicAdd(&g_done, 1u);
            if (t == NBLOCKS_ - 1u) {
                // every contributing block fenced its add before its done-increment
                const double total = *((volatile double*)&g_sum);
                *out = (float)(total / (double)B_);
                g_sum = 0.0;               // reset for next graph replay
                __threadfence();
                g_done = 0u;
            }
        }
    }
}

extern "C" void kernel_launch(void* const* d_in, const int* in_sizes, int n_in,
                              void* d_out, int out_size)
{
    const float* imgs_box   = (const float*)d_in[0];
    const int*   img_labels = (const int*)  d_in[1];
    const float* pre_BOX    = (const float*)d_in[2];
    const int*   pre_label  = (const int*)  d_in[3];
    float* out = (float*)d_out;

    dim3 grid(CHUNKS_, B_);
    fused_giou_kernel<<<grid, 256>>>(imgs_box, img_labels, pre_BOX, pre_label, out);
}